// round 9
// baseline (speedup 1.0000x reference)
#include <cuda_runtime.h>
#include <cuda_fp16.h>
#include <cstdint>
#include <cstddef>

#define TSTEPS 512
#define INDIM  22
#define HDIM   64
#define NTHR   256
#define NBLK   152
#define KT     6             // k-tiles of 16: 2 x-tiles (32 padded cols), 4 h-tiles
#define GF4    (KT * 32)     // float4 slots per A buffer per group (192 = 3072 B)

__device__ __forceinline__ float tanhapx(float x) {
    float y; asm("tanh.approx.f32 %0, %1;" : "=f"(y) : "f"(x)); return y;
}
__device__ __forceinline__ float sigapx(float x) {
    return fmaf(tanhapx(0.5f * x), 0.5f, 0.5f);
}
__device__ __forceinline__ uint32_t packh2(float lo, float hi) {
    __half2 h = __floats2half2_rn(lo, hi);
    return *(uint32_t*)&h;
}

// D += A(16x16,row) * B(16x8,col); fp16 inputs, f32 accum
#define MMA16(d, a, b0, b1)                                                 \
    asm volatile("mma.sync.aligned.m16n8k16.row.col.f32.f16.f16.f32 "       \
        "{%0,%1,%2,%3}, {%4,%5,%6,%7}, {%8,%9}, {%0,%1,%2,%3};"             \
        : "+f"((d)[0]), "+f"((d)[1]), "+f"((d)[2]), "+f"((d)[3])            \
        : "r"(__float_as_uint((a).x)), "r"(__float_as_uint((a).y)),         \
          "r"(__float_as_uint((a).z)), "r"(__float_as_uint((a).w)),         \
          "r"(b0), "r"(b1))

__global__ __launch_bounds__(NTHR, 1)
void lstm_mma_kernel(const float* __restrict__ in,
                     const float* __restrict__ Wih,
                     const float* __restrict__ Whh,
                     const float* __restrict__ bih,
                     const float* __restrict__ bhh,
                     float* __restrict__ out)
{
    __shared__ float4 Abuf[2][2][GF4];       // [group][buf][frag]

    const int tid = threadIdx.x;
    const int bid = blockIdx.x;
    const int w   = tid >> 5;
    const int l   = tid & 31;
    const int g   = w >> 2;        // group 0: rows 0-15, group 1: rows 16-31
    const int wg  = w & 3;         // warp-in-group -> 16-unit slab
    const int gt  = tid & 127;     // thread-in-group

    const int R        = (bid < 144) ? 27 : 26;     // 4096 = 144*27 + 8*26
    const int rowStart = (bid < 144) ? bid * 27 : 144 * 27 + (bid - 144) * 26;
    const int grpRow0  = g * 16;
    const int RG       = g ? (R - 16) : 16;         // real rows in this group

    // ---- zero both groups' A buffers ----
    for (int i = tid; i < 2 * 2 * GF4; i += NTHR)
        ((float4*)Abuf)[i] = make_float4(0.f, 0.f, 0.f, 0.f);

    // ---- B fragments: this warp covers 16 units x 4 gates = 8 n-tiles ----
    const int ub = wg * 16;
    uint32_t bw[KT][8][2];
    {
        const int k0 = (l & 3) * 2;
#pragma unroll
        for (int kt = 0; kt < KT; kt++) {
#pragma unroll
            for (int gate = 0; gate < 4; gate++) {
#pragma unroll
                for (int th = 0; th < 2; th++) {
                    const int n = gate * 64 + ub + th * 8 + (l >> 2);
                    if (kt < 2) {
                        int ka = kt * 16 + k0, kb = ka + 8;
                        float a0 = (ka     < INDIM) ? Wih[n * INDIM + ka]     : 0.f;
                        float a1 = (ka + 1 < INDIM) ? Wih[n * INDIM + ka + 1] : 0.f;
                        float b0 = (kb     < INDIM) ? Wih[n * INDIM + kb]     : 0.f;
                        float b1 = (kb + 1 < INDIM) ? Wih[n * INDIM + kb + 1] : 0.f;
                        bw[kt][gate * 2 + th][0] = packh2(a0, a1);
                        bw[kt][gate * 2 + th][1] = packh2(b0, b1);
                    } else {
                        int ka = (kt - 2) * 16 + k0;
                        bw[kt][gate * 2 + th][0] =
                            packh2(Whh[n * HDIM + ka],     Whh[n * HDIM + ka + 1]);
                        bw[kt][gate * 2 + th][1] =
                            packh2(Whh[n * HDIM + ka + 8], Whh[n * HDIM + ka + 9]);
                    }
                }
            }
        }
    }

    // ---- biases: bb[nt][j] for lane's unit = ub + th*8 + 2*(l&3) + j ----
    float bb[8][2];
#pragma unroll
    for (int gate = 0; gate < 4; gate++)
#pragma unroll
        for (int th = 0; th < 2; th++)
#pragma unroll
            for (int j = 0; j < 2; j++) {
                int u = ub + th * 8 + 2 * (l & 3) + j;
                bb[gate * 2 + th][j] = bih[gate * 64 + u] + bhh[gate * 64 + u];
            }

    // ---- h write-back u32 slots: (rh, ph) -> half2 (units p, p+1) ----
    int hoff[2][2];
#pragma unroll
    for (int rh = 0; rh < 2; rh++)
#pragma unroll
        for (int ph = 0; ph < 2; ph++) {
            int p   = ub + ph * 8 + 2 * (l & 3);
            int kt  = 2 + (p >> 4);
            int tc  = p & 15;
            int lp  = (l >> 2) * 4 + ((tc & 7) >> 1);
            hoff[rh][ph] = (kt * 32 + lp) * 4 + (rh | ((tc >> 3) << 1));
        }

    // ---- x feed slots (group-local; 3 per thread covers 16*22=352) ----
    const int NXL = 3;
    const float* xp[NXL];
    bool xv[NXL];
    int  xoff[NXL];
#pragma unroll
    for (int q = 0; q < NXL; q++) {
        int idx = gt + q * 128;
        xv[q] = (idx < RG * INDIM);
        int r  = xv[q] ? idx / INDIM : 0;
        int i2 = xv[q] ? idx - r * INDIM : 0;
        xp[q] = in + (size_t)(rowStart + grpRow0 + r) * TSTEPS * INDIM + i2;
        int kt = i2 >> 4, tc = i2 & 15;
        int lp   = (r & 7) * 4 + ((tc & 7) >> 1);
        int slot = (r >> 3) | ((tc >> 3) << 1);
        xoff[q] = ((kt * 32 + lp) * 4 + slot) * 2 + (tc & 1);
    }

    __syncthreads();

    // ---- stage x(0) ----
#pragma unroll
    for (int q = 0; q < NXL; q++)
        if (xv[q]) ((__half*)Abuf[g][0])[xoff[q]] = __float2half_rn(xp[q][0]);
    __syncthreads();

    float cst[2][2][2];
#pragma unroll
    for (int i = 0; i < 8; i++) ((float*)cst)[i] = 0.0f;

    const float* outrow = out + (size_t)(rowStart + grpRow0) * TSTEPS * HDIM;
    const int barid = 1 + g;

    // ================= main recurrence (independent per group) =================
#pragma unroll 1
    for (int t = 0; t < TSTEPS; t++) {
        const float4* Ac = Abuf[g][t & 1];
        uint32_t*     An = (uint32_t*)Abuf[g][(t + 1) & 1];

        float xr[NXL];
        if (t + 1 < TSTEPS) {
#pragma unroll
            for (int q = 0; q < NXL; q++)
                xr[q] = xv[q] ? xp[q][(size_t)(t + 1) * INDIM] : 0.0f;
        }

        // ---- gates = bias + [x|h] W^T via 48 HMMA ----
        float acc[8][4];
#pragma unroll
        for (int nt = 0; nt < 8; nt++)
#pragma unroll
            for (int s = 0; s < 4; s++)
                acc[nt][s] = bb[nt][s & 1];

#pragma unroll
        for (int kt = 0; kt < KT; kt++) {
            float4 a = Ac[kt * 32 + l];
#pragma unroll
            for (int nt = 0; nt < 8; nt++)
                MMA16(acc[nt], a, bw[kt][nt][0], bw[kt][nt][1]);
        }

        // ---- pointwise LSTM cell, in registers ----
#pragma unroll
        for (int rh = 0; rh < 2; rh++) {
            const int mrow = rh * 8 + (l >> 2);
#pragma unroll
            for (int ph = 0; ph < 2; ph++) {
                float h2[2];
#pragma unroll
                for (int j = 0; j < 2; j++) {
                    const int s = rh * 2 + j;
                    float iv = sigapx(acc[0 + ph][s]);
                    float fv = sigapx(acc[2 + ph][s]);
                    float gv = tanhapx(acc[4 + ph][s]);
                    float ov = sigapx(acc[6 + ph][s]);
                    float cn = fmaf(fv, cst[rh][ph][j], iv * gv);
                    cst[rh][ph][j] = cn;
                    h2[j] = ov * tanhapx(cn);
                }
                An[hoff[rh][ph]] = packh2(h2[0], h2[1]);
                if (mrow < RG) {
                    const int p = ub + ph * 8 + 2 * (l & 3);
                    *(float2*)((float*)outrow + (size_t)mrow * TSTEPS * HDIM
                               + (size_t)t * HDIM + p) = make_float2(h2[0], h2[1]);
                }
            }
        }

        // publish x(t+1)
        if (t + 1 < TSTEPS) {
#pragma unroll
            for (int q = 0; q < NXL; q++)
                if (xv[q]) ((__half*)An)[xoff[q]] = __float2half_rn(xr[q]);
        }

        // group-private barrier (128 threads)
        asm volatile("bar.sync %0, %1;" :: "r"(barid), "r"(128) : "memory");
    }
}

extern "C" void kernel_launch(void* const* d_in, const int* in_sizes, int n_in,
                              void* d_out, int out_size)
{
    const float* in  = (const float*)d_in[0];
    const float* Wih = (const float*)d_in[1];
    const float* Whh = (const float*)d_in[2];
    const float* bih = (const float*)d_in[3];
    const float* bhh = (const float*)d_in[4];
    float* out = (float*)d_out;

    lstm_mma_kernel<<<NBLK, NTHR>>>(in, Wih, Whh, bih, bhh, out);
}

// round 13
// speedup vs baseline: 1.5666x; 1.5666x over previous
#include <cuda_runtime.h>
#include <cuda_fp16.h>
#include <cstdint>
#include <cstddef>

#define TSTEPS 512
#define INDIM  22
#define HDIM   64
#define NTHR   256
#define NBLK   152
#define KTX    2             // x k-tiles of 16 (32 padded cols)
#define KTH    4             // h k-tiles of 16 (64 cols)
#define XF4    (KTX * 2 * 32)   // float4 frags per x buffer (128 = 2KB)
#define HF4    (KTH * 2 * 32)   // float4 frags per h buffer (256 = 4KB)

__device__ __forceinline__ float tanhapx(float x) {
    float y; asm("tanh.approx.f32 %0, %1;" : "=f"(y) : "f"(x)); return y;
}
__device__ __forceinline__ float sigapx(float x) {
    return fmaf(tanhapx(0.5f * x), 0.5f, 0.5f);
}
__device__ __forceinline__ uint32_t packh2(float lo, float hi) {
    __half2 h = __floats2half2_rn(lo, hi);
    return *(uint32_t*)&h;
}

// D += A(16x16,row) * B(16x8,col); fp16 inputs, f32 accum
#define MMA16(d, a, b0, b1)                                                 \
    asm volatile("mma.sync.aligned.m16n8k16.row.col.f32.f16.f16.f32 "       \
        "{%0,%1,%2,%3}, {%4,%5,%6,%7}, {%8,%9}, {%0,%1,%2,%3};"             \
        : "+f"((d)[0]), "+f"((d)[1]), "+f"((d)[2]), "+f"((d)[3])            \
        : "r"(__float_as_uint((a).x)), "r"(__float_as_uint((a).y)),         \
          "r"(__float_as_uint((a).z)), "r"(__float_as_uint((a).w)),         \
          "r"(b0), "r"(b1))

__global__ __launch_bounds__(NTHR, 1)
void lstm_mma_kernel(const float* __restrict__ in,
                     const float* __restrict__ Wih,
                     const float* __restrict__ Whh,
                     const float* __restrict__ bih,
                     const float* __restrict__ bhh,
                     float* __restrict__ out)
{
    __shared__ float4 Xbuf[2][XF4];   // x fragments, staged 2 steps ahead
    __shared__ float4 Hbuf[2][HF4];   // h fragments, double-buffered

    const int tid = threadIdx.x;
    const int bid = blockIdx.x;
    const int w   = tid >> 5;      // warp -> unit slab w*8..w*8+7
    const int l   = tid & 31;

    const int R        = (bid < 144) ? 27 : 26;     // 4096 = 144*27 + 8*26
    const int rowStart = (bid < 144) ? bid * 27 : 144 * 27 + (bid - 144) * 26;

    // ---- zero buffers (padding rows/cols stay zero; h(-1)=0) ----
    for (int i = tid; i < 2 * XF4; i += NTHR)
        ((float4*)Xbuf)[i] = make_float4(0.f, 0.f, 0.f, 0.f);
    for (int i = tid; i < 2 * HF4; i += NTHR)
        ((float4*)Hbuf)[i] = make_float4(0.f, 0.f, 0.f, 0.f);

    // ---- B fragments (fp16) ----
    uint32_t bwx[KTX][4][2], bwh[KTH][4][2];
    {
        const int nu = w * 8 + (l >> 2);
        const int k0 = (l & 3) * 2;
#pragma unroll
        for (int kt = 0; kt < KTX; kt++)
#pragma unroll
            for (int nt = 0; nt < 4; nt++) {
                const int n = nt * 64 + nu;
                int ka = kt * 16 + k0, kb = ka + 8;
                float a0 = (ka     < INDIM) ? Wih[n * INDIM + ka]     : 0.f;
                float a1 = (ka + 1 < INDIM) ? Wih[n * INDIM + ka + 1] : 0.f;
                float b0 = (kb     < INDIM) ? Wih[n * INDIM + kb]     : 0.f;
                float b1 = (kb + 1 < INDIM) ? Wih[n * INDIM + kb + 1] : 0.f;
                bwx[kt][nt][0] = packh2(a0, a1);
                bwx[kt][nt][1] = packh2(b0, b1);
            }
#pragma unroll
        for (int kt = 0; kt < KTH; kt++)
#pragma unroll
            for (int nt = 0; nt < 4; nt++) {
                const int n = nt * 64 + nu;
                int ka = kt * 16 + k0;
                bwh[kt][nt][0] = packh2(Whh[n * HDIM + ka],     Whh[n * HDIM + ka + 1]);
                bwh[kt][nt][1] = packh2(Whh[n * HDIM + ka + 8], Whh[n * HDIM + ka + 9]);
            }
    }

    // ---- biases (folded into acc init) ----
    const int u0 = w * 8 + 2 * (l & 3);
    float bb[4][2];
#pragma unroll
    for (int g = 0; g < 4; g++) {
        bb[g][0] = bih[g * 64 + u0]     + bhh[g * 64 + u0];
        bb[g][1] = bih[g * 64 + u0 + 1] + bhh[g * 64 + u0 + 1];
    }

    // ---- h write-back u32 slots inside Hbuf ----
    int hoff[2][2];
    {
        const int ktH = u0 >> 4;
        const int tc  = u0 & 15;
        const int lp  = (l >> 2) * 4 + ((tc & 7) >> 1);
#pragma unroll
        for (int mt = 0; mt < 2; mt++)
#pragma unroll
            for (int rh = 0; rh < 2; rh++)
                hoff[mt][rh] = (((ktH * 2 + mt) * 32 + lp) * 4) + (rh | ((tc >> 3) << 1));
    }

    // ---- x feed slots (3 per thread covers R*INDIM <= 594), half-index in Xbuf ----
    const int NXL = 3;
    const float* xp[NXL];
    bool xv[NXL];
    int  xoff[NXL];
#pragma unroll
    for (int q = 0; q < NXL; q++) {
        int idx = tid + q * NTHR;
        xv[q] = (idx < R * INDIM);
        int r  = xv[q] ? idx / INDIM : 0;
        int i2 = xv[q] ? idx - r * INDIM : 0;
        xp[q] = in + (size_t)(rowStart + r) * TSTEPS * INDIM + i2;
        int mt = r >> 4, rr = r & 15, ktx = i2 >> 4, tc = i2 & 15;
        int lp   = (rr & 7) * 4 + ((tc & 7) >> 1);
        int slot = (rr >> 3) | ((tc >> 3) << 1);
        xoff[q] = ((((ktx * 2 + mt) * 32 + lp) * 4) + slot) * 2 + (tc & 1);
    }

    __syncthreads();

    // ---- stage x(0) -> Xbuf[0], x(1) -> Xbuf[1] ----
#pragma unroll
    for (int q = 0; q < NXL; q++)
        if (xv[q]) {
            ((__half*)Xbuf[0])[xoff[q]] = __float2half_rn(xp[q][0]);
            ((__half*)Xbuf[1])[xoff[q]] = __float2half_rn(xp[q][(size_t)INDIM]);
        }
    __syncthreads();

    float cst[2][2][2];
#pragma unroll
    for (int i = 0; i < 8; i++) ((float*)cst)[i] = 0.0f;

    float* outp = out + (size_t)rowStart * TSTEPS * HDIM + u0;

    // ---- acc_a = bias + x(0)-part (reads Xbuf[0]) ----
    float acc_a[2][4][4], acc_b[2][4][4];
#pragma unroll
    for (int mt = 0; mt < 2; mt++)
#pragma unroll
        for (int nt = 0; nt < 4; nt++)
#pragma unroll
            for (int s = 0; s < 4; s++)
                acc_a[mt][nt][s] = bb[nt][s & 1];
#pragma unroll
    for (int kt = 0; kt < KTX; kt++) {
        float4 a0 = Xbuf[0][(kt * 2 + 0) * 32 + l];
        float4 a1 = Xbuf[0][(kt * 2 + 1) * 32 + l];
#pragma unroll
        for (int nt = 0; nt < 4; nt++) {
            MMA16(acc_a[0][nt], a0, bwx[kt][nt][0], bwx[kt][nt][1]);
            MMA16(acc_a[1][nt], a1, bwx[kt][nt][0], bwx[kt][nt][1]);
        }
    }
    // RACE FIX (R10 bug): all warps must finish reading x(0) from Xbuf[0]
    // before STEP(0) publishes x(2) into the same buffer.
    __syncthreads();

    // ================= main recurrence (2 steps per trip) =================
    // STEP(t): accC holds bias + x(t)-part; h(t-1) in Hbuf[t&1];
    //          x(t+1) in Xbuf[(t+1)&1] (published step t-1);
    //          computes accN = bias + x(t+1)-part; stages x(t+2) -> Xbuf[t&1];
    //          pointwise -> h(t) into Hbuf[(t+1)&1] + GMEM out.
#define STEP(T, accC, accN)                                                   \
    {                                                                          \
        const int t = (T);                                                     \
        const float4* Hc = Hbuf[t & 1];                                        \
        const float4* Xn = Xbuf[(t + 1) & 1];                                  \
        uint32_t*     Hw = (uint32_t*)Hbuf[(t + 1) & 1];                       \
        __half*       Xw = (__half*)Xbuf[t & 1];                               \
        /* LDG x(t+2) early (hidden) */                                        \
        float xr[NXL];                                                         \
        if (t + 2 < TSTEPS) {                                                  \
            _Pragma("unroll")                                                  \
            for (int q = 0; q < NXL; q++)                                      \
                xr[q] = xv[q] ? xp[q][(size_t)(t + 2) * INDIM] : 0.0f;         \
        }                                                                      \
        /* h-part MMA into accC */                                             \
        _Pragma("unroll")                                                      \
        for (int kt = 0; kt < KTH; kt++) {                                     \
            float4 a0 = Hc[(kt * 2 + 0) * 32 + l];                             \
            float4 a1 = Hc[(kt * 2 + 1) * 32 + l];                             \
            _Pragma("unroll")                                                  \
            for (int nt = 0; nt < 4; nt++) {                                   \
                MMA16(accC[0][nt], a0, bwh[kt][nt][0], bwh[kt][nt][1]);        \
                MMA16(accC[1][nt], a1, bwh[kt][nt][0], bwh[kt][nt][1]);        \
            }                                                                  \
        }                                                                      \
        /* accN = bias + x(t+1)-part (independent of pointwise below) */       \
        _Pragma("unroll")                                                      \
        for (int mt = 0; mt < 2; mt++)                                         \
            _Pragma("unroll")                                                  \
            for (int nt = 0; nt < 4; nt++)                                     \
                _Pragma("unroll")                                              \
                for (int s = 0; s < 4; s++)                                    \
                    accN[mt][nt][s] = bb[nt][s & 1];                           \
        _Pragma("unroll")                                                      \
        for (int kt = 0; kt < KTX; kt++) {                                     \
            float4 a0 = Xn[(kt * 2 + 0) * 32 + l];                             \
            float4 a1 = Xn[(kt * 2 + 1) * 32 + l];                             \
            _Pragma("unroll")                                                  \
            for (int nt = 0; nt < 4; nt++) {                                   \
                MMA16(accN[0][nt], a0, bwx[kt][nt][0], bwx[kt][nt][1]);        \
                MMA16(accN[1][nt], a1, bwx[kt][nt][0], bwx[kt][nt][1]);        \
            }                                                                  \
        }                                                                      \
        /* pointwise on accC (MUFU chain; x-MMA above fills the pipe) */       \
        _Pragma("unroll")                                                      \
        for (int mt = 0; mt < 2; mt++) {                                       \
            _Pragma("unroll")                                                  \
            for (int rh = 0; rh < 2; rh++) {                                   \
                const int row = mt * 16 + rh * 8 + (l >> 2);                   \
                float h2[2];                                                   \
                _Pragma("unroll")                                              \
                for (int j = 0; j < 2; j++) {                                  \
                    const int s = rh * 2 + j;                                  \
                    float iv = sigapx(accC[mt][0][s]);                         \
                    float fv = sigapx(accC[mt][1][s]);                         \
                    float gv = tanhapx(accC[mt][2][s]);                        \
                    float ov = sigapx(accC[mt][3][s]);                         \
                    float cn = fmaf(fv, cst[mt][rh][j], iv * gv);              \
                    cst[mt][rh][j] = cn;                                       \
                    h2[j] = ov * tanhapx(cn);                                  \
                }                                                              \
                Hw[hoff[mt][rh]] = packh2(h2[0], h2[1]);                       \
                if (row < R)                                                   \
                    *(float2*)(outp + (size_t)row * TSTEPS * HDIM              \
                               + (size_t)t * HDIM) = make_float2(h2[0], h2[1]);\
            }                                                                  \
        }                                                                      \
        /* publish x(t+2) */                                                   \
        if (t + 2 < TSTEPS) {                                                  \
            _Pragma("unroll")                                                  \
            for (int q = 0; q < NXL; q++)                                      \
                if (xv[q]) Xw[xoff[q]] = __float2half_rn(xr[q]);               \
        }                                                                      \
        __syncthreads();                                                       \
    }

#pragma unroll 1
    for (int tt = 0; tt < TSTEPS / 2; tt++) {
        STEP(2 * tt,     acc_a, acc_b);
        STEP(2 * tt + 1, acc_b, acc_a);
    }
#undef STEP
}

extern "C" void kernel_launch(void* const* d_in, const int* in_sizes, int n_in,
                              void* d_out, int out_size)
{
    const float* in  = (const float*)d_in[0];
    const float* Wih = (const float*)d_in[1];
    const float* Whh = (const float*)d_in[2];
    const float* bih = (const float*)d_in[3];
    const float* bhh = (const float*)d_in[4];
    float* out = (float*)d_out;

    lstm_mma_kernel<<<NBLK, NTHR>>>(in, Wih, Whh, bih, bhh, out);
}

// round 14
// speedup vs baseline: 1.7257x; 1.1016x over previous
#include <cuda_runtime.h>
#include <cuda_fp16.h>
#include <cstdint>
#include <cstddef>

#define TSTEPS 512
#define INDIM  22
#define HDIM   64
#define NTHR   256
#define NBLK   304           // 2 CTAs per SM; 4096 = 144*14 + 160*13
#define KTX    2             // x k-tiles of 16 (32 padded cols)
#define KTH    4             // h k-tiles of 16 (64 cols)
#define XF4    (KTX * 32)    // float4 frags per x buffer (64 = 1KB)
#define HF4    (KTH * 32)    // float4 frags per h buffer (128 = 2KB)

__device__ __forceinline__ float tanhapx(float x) {
    float y; asm("tanh.approx.f32 %0, %1;" : "=f"(y) : "f"(x)); return y;
}
__device__ __forceinline__ float sigapx(float x) {
    return fmaf(tanhapx(0.5f * x), 0.5f, 0.5f);
}
__device__ __forceinline__ uint32_t packh2(float lo, float hi) {
    __half2 h = __floats2half2_rn(lo, hi);
    return *(uint32_t*)&h;
}

// D += A(16x16,row) * B(16x8,col); fp16 inputs, f32 accum
#define MMA16(d, a, b0, b1)                                                 \
    asm volatile("mma.sync.aligned.m16n8k16.row.col.f32.f16.f16.f32 "       \
        "{%0,%1,%2,%3}, {%4,%5,%6,%7}, {%8,%9}, {%0,%1,%2,%3};"             \
        : "+f"((d)[0]), "+f"((d)[1]), "+f"((d)[2]), "+f"((d)[3])            \
        : "r"(__float_as_uint((a).x)), "r"(__float_as_uint((a).y)),         \
          "r"(__float_as_uint((a).z)), "r"(__float_as_uint((a).w)),         \
          "r"(b0), "r"(b1))

__global__ __launch_bounds__(NTHR, 2)
void lstm_mma_kernel(const float* __restrict__ in,
                     const float* __restrict__ Wih,
                     const float* __restrict__ Whh,
                     const float* __restrict__ bih,
                     const float* __restrict__ bhh,
                     float* __restrict__ out)
{
    __shared__ float4 Xbuf[2][XF4];   // x fragments, staged 2 steps ahead
    __shared__ float4 Hbuf[2][HF4];   // h fragments, double-buffered

    const int tid = threadIdx.x;
    const int bid = blockIdx.x;
    const int w   = tid >> 5;      // warp -> unit slab w*8..w*8+7
    const int l   = tid & 31;

    const int R        = (bid < 144) ? 14 : 13;     // 4096 = 144*14 + 160*13
    const int rowStart = (bid < 144) ? bid * 14 : 144 * 14 + (bid - 144) * 13;

    // ---- zero buffers (padding rows/cols stay zero; h(-1)=0) ----
    for (int i = tid; i < 2 * XF4; i += NTHR)
        ((float4*)Xbuf)[i] = make_float4(0.f, 0.f, 0.f, 0.f);
    for (int i = tid; i < 2 * HF4; i += NTHR)
        ((float4*)Hbuf)[i] = make_float4(0.f, 0.f, 0.f, 0.f);

    // ---- B fragments (fp16, register-resident) ----
    uint32_t bwx[KTX][4][2], bwh[KTH][4][2];
    {
        const int nu = w * 8 + (l >> 2);
        const int k0 = (l & 3) * 2;
#pragma unroll
        for (int kt = 0; kt < KTX; kt++)
#pragma unroll
            for (int nt = 0; nt < 4; nt++) {
                const int n = nt * 64 + nu;
                int ka = kt * 16 + k0, kb = ka + 8;
                float a0 = (ka     < INDIM) ? Wih[n * INDIM + ka]     : 0.f;
                float a1 = (ka + 1 < INDIM) ? Wih[n * INDIM + ka + 1] : 0.f;
                float b0 = (kb     < INDIM) ? Wih[n * INDIM + kb]     : 0.f;
                float b1 = (kb + 1 < INDIM) ? Wih[n * INDIM + kb + 1] : 0.f;
                bwx[kt][nt][0] = packh2(a0, a1);
                bwx[kt][nt][1] = packh2(b0, b1);
            }
#pragma unroll
        for (int kt = 0; kt < KTH; kt++)
#pragma unroll
            for (int nt = 0; nt < 4; nt++) {
                const int n = nt * 64 + nu;
                int ka = kt * 16 + k0;
                bwh[kt][nt][0] = packh2(Whh[n * HDIM + ka],     Whh[n * HDIM + ka + 1]);
                bwh[kt][nt][1] = packh2(Whh[n * HDIM + ka + 8], Whh[n * HDIM + ka + 9]);
            }
    }

    // ---- biases (folded into acc init) ----
    const int u0 = w * 8 + 2 * (l & 3);
    float bb[4][2];
#pragma unroll
    for (int g = 0; g < 4; g++) {
        bb[g][0] = bih[g * 64 + u0]     + bhh[g * 64 + u0];
        bb[g][1] = bih[g * 64 + u0 + 1] + bhh[g * 64 + u0 + 1];
    }

    // ---- h write-back u32 slots inside Hbuf (single m-tile) ----
    int hoff[2];
    {
        const int ktH = u0 >> 4;
        const int tc  = u0 & 15;
        const int lp  = (l >> 2) * 4 + ((tc & 7) >> 1);
#pragma unroll
        for (int rh = 0; rh < 2; rh++)
            hoff[rh] = ((ktH * 32 + lp) * 4) + (rh | ((tc >> 3) << 1));
    }

    // ---- x feed slots (2 per thread covers R*INDIM <= 308) ----
    const int NXL = 2;
    const float* xp[NXL];
    bool xv[NXL];
    int  xoff[NXL];
#pragma unroll
    for (int q = 0; q < NXL; q++) {
        int idx = tid + q * NTHR;
        xv[q] = (idx < R * INDIM);
        int r  = xv[q] ? idx / INDIM : 0;
        int i2 = xv[q] ? idx - r * INDIM : 0;
        xp[q] = in + (size_t)(rowStart + r) * TSTEPS * INDIM + i2;
        int ktx = i2 >> 4, tc = i2 & 15;
        int lp   = (r & 7) * 4 + ((tc & 7) >> 1);
        int slot = (r >> 3) | ((tc >> 3) << 1);
        xoff[q] = (((ktx * 32 + lp) * 4) + slot) * 2 + (tc & 1);
    }

    __syncthreads();

    // ---- stage x(0) -> Xbuf[0], x(1) -> Xbuf[1] ----
#pragma unroll
    for (int q = 0; q < NXL; q++)
        if (xv[q]) {
            ((__half*)Xbuf[0])[xoff[q]] = __float2half_rn(xp[q][0]);
            ((__half*)Xbuf[1])[xoff[q]] = __float2half_rn(xp[q][(size_t)INDIM]);
        }
    __syncthreads();

    float cst[2][2];
#pragma unroll
    for (int i = 0; i < 4; i++) ((float*)cst)[i] = 0.0f;

    float* outp = out + (size_t)rowStart * TSTEPS * HDIM + u0;

    // ---- acc_a = bias + x(0)-part (reads Xbuf[0]) ----
    float acc_a[4][4], acc_b[4][4];
#pragma unroll
    for (int nt = 0; nt < 4; nt++)
#pragma unroll
        for (int s = 0; s < 4; s++)
            acc_a[nt][s] = bb[nt][s & 1];
#pragma unroll
    for (int kt = 0; kt < KTX; kt++) {
        float4 a = Xbuf[0][kt * 32 + l];
#pragma unroll
        for (int nt = 0; nt < 4; nt++)
            MMA16(acc_a[nt], a, bwx[kt][nt][0], bwx[kt][nt][1]);
    }
    // Race guard: all warps must finish reading x(0) from Xbuf[0]
    // before STEP(0) publishes x(2) into the same buffer.
    __syncthreads();

    // ================= main recurrence (2 steps per trip) =================
#define STEP(T, accC, accN)                                                   \
    {                                                                          \
        const int t = (T);                                                     \
        const float4* Hc = Hbuf[t & 1];                                        \
        const float4* Xn = Xbuf[(t + 1) & 1];                                  \
        uint32_t*     Hw = (uint32_t*)Hbuf[(t + 1) & 1];                       \
        __half*       Xw = (__half*)Xbuf[t & 1];                               \
        float xr[NXL];                                                         \
        if (t + 2 < TSTEPS) {                                                  \
            _Pragma("unroll")                                                  \
            for (int q = 0; q < NXL; q++)                                      \
                xr[q] = xv[q] ? xp[q][(size_t)(t + 2) * INDIM] : 0.0f;         \
        }                                                                      \
        /* h-part MMA into accC */                                             \
        _Pragma("unroll")                                                      \
        for (int kt = 0; kt < KTH; kt++) {                                     \
            float4 a = Hc[kt * 32 + l];                                        \
            _Pragma("unroll")                                                  \
            for (int nt = 0; nt < 4; nt++)                                     \
                MMA16(accC[nt], a, bwh[kt][nt][0], bwh[kt][nt][1]);            \
        }                                                                      \
        /* accN = bias + x(t+1)-part (independent of pointwise below) */       \
        _Pragma("unroll")                                                      \
        for (int nt = 0; nt < 4; nt++)                                         \
            _Pragma("unroll")                                                  \
            for (int s = 0; s < 4; s++)                                        \
                accN[nt][s] = bb[nt][s & 1];                                   \
        _Pragma("unroll")                                                      \
        for (int kt = 0; kt < KTX; kt++) {                                     \
            float4 a = Xn[kt * 32 + l];                                        \
            _Pragma("unroll")                                                  \
            for (int nt = 0; nt < 4; nt++)                                     \
                MMA16(accN[nt], a, bwx[kt][nt][0], bwx[kt][nt][1]);            \
        }                                                                      \
        /* pointwise on accC (x-MMA above fills the tensor pipe) */            \
        _Pragma("unroll")                                                      \
        for (int rh = 0; rh < 2; rh++) {                                       \
            const int row = rh * 8 + (l >> 2);                                 \
            float h2[2];                                                       \
            _Pragma("unroll")                                                  \
            for (int j = 0; j < 2; j++) {                                      \
                const int s = rh * 2 + j;                                      \
                float iv = sigapx(accC[0][s]);                                 \
                float fv = sigapx(accC[1][s]);                                 \
                float gv = tanhapx(accC[2][s]);                                \
                float ov = sigapx(accC[3][s]);                                 \
                float cn = fmaf(fv, cst[rh][j], iv * gv);                      \
                cst[rh][j] = cn;                                               \
                h2[j] = ov * tanhapx(cn);                                      \
            }                                                                  \
            Hw[hoff[rh]] = packh2(h2[0], h2[1]);                               \
            if (row < R)                                                       \
                *(float2*)(outp + (size_t)row * TSTEPS * HDIM                  \
                           + (size_t)t * HDIM) = make_float2(h2[0], h2[1]);    \
        }                                                                      \
        /* publish x(t+2) */                                                   \
        if (t + 2 < TSTEPS) {                                                  \
            _Pragma("unroll")                                                  \
            for (int q = 0; q < NXL; q++)                                      \
                if (xv[q]) Xw[xoff[q]] = __float2half_rn(xr[q]);               \
        }                                                                      \
        __syncthreads();                                                       \
    }

#pragma unroll 1
    for (int tt = 0; tt < TSTEPS / 2; tt++) {
        STEP(2 * tt,     acc_a, acc_b);
        STEP(2 * tt + 1, acc_b, acc_a);
    }
#undef STEP
}

extern "C" void kernel_launch(void* const* d_in, const int* in_sizes, int n_in,
                              void* d_out, int out_size)
{
    const float* in  = (const float*)d_in[0];
    const float* Wih = (const float*)d_in[1];
    const float* Whh = (const float*)d_in[2];
    const float* bih = (const float*)d_in[3];
    const float* bhh = (const float*)d_in[4];
    float* out = (float*)d_out;

    lstm_mma_kernel<<<NBLK, NTHR>>>(in, Wih, Whh, bih, bhh, out);
}